// round 5
// baseline (speedup 1.0000x reference)
#include <cuda_runtime.h>
#include <cuda_bf16.h>
#include <cstdint>

// ---------------------------------------------------------------------------
// Problem constants
// ---------------------------------------------------------------------------
#define DIN   4096
#define DOUT  4096
#define MTOT  8192
#define BK    64                          // bf16 k-elems per chunk (128 B/row)
#define NCHUNK ((DIN / BK) * 3)           // 192 (3 segments: hi*hi, lo*hi, hi*lo)
#define BM    128
#define BN    256
#define NSTAGE 4
#define A_BYTES 16384                     // 128 rows * 128 B
#define B_BYTES 32768                     // 256 rows * 128 B
#define STAGE_BYTES (A_BYTES + B_BYTES)   // 48 KB
#define SMEM_TOTAL (NSTAGE * STAGE_BYTES) // 192 KB
static __device__ __constant__ float kScaling = 2.0f;   // 32 / rank(16)

// ---------------------------------------------------------------------------
// Device-global scratch
// ---------------------------------------------------------------------------
__device__ __nv_bfloat16 g_Xhi[(size_t)MTOT * DIN];
__device__ __nv_bfloat16 g_Xlo[(size_t)MTOT * DIN];
__device__ __nv_bfloat16 g_Whi[(size_t)DOUT * DIN];
__device__ __nv_bfloat16 g_Wlo[(size_t)DOUT * DIN];
__device__ int g_flags[2];
__device__ int g_mode;

// ---------------------------------------------------------------------------
// Helpers (baseline PTX only — compiles at compute_103)
// ---------------------------------------------------------------------------
__device__ __forceinline__ uint32_t smem_u32(const void* p) {
    uint32_t a;
    asm("{ .reg .u64 t; cvta.to.shared.u64 t, %1; cvt.u32.u64 %0, t; }" : "=r"(a) : "l"(p));
    return a;
}
__device__ __forceinline__ void cp_async16(uint32_t dst, const void* src) {
    asm volatile("cp.async.cg.shared.global [%0], [%1], 16;"
                 :: "r"(dst), "l"(__cvta_generic_to_global(src)));
}
#define CP_COMMIT() asm volatile("cp.async.commit_group;" ::: "memory")
#define CP_WAIT(n)  asm volatile("cp.async.wait_group %0;" :: "n"(n) : "memory")

__device__ __forceinline__ uint32_t swz(uint32_t o) { return o ^ ((o >> 3) & 0x70); }

__device__ __forceinline__ void ldsm_x4(uint32_t* r, uint32_t addr) {
    asm volatile("ldmatrix.sync.aligned.m8n8.x4.shared.b16 {%0,%1,%2,%3}, [%4];"
                 : "=r"(r[0]), "=r"(r[1]), "=r"(r[2]), "=r"(r[3]) : "r"(addr));
}
__device__ __forceinline__ void mma_bf16(float* c, const uint32_t* a,
                                         uint32_t b0, uint32_t b1) {
    asm volatile(
        "mma.sync.aligned.m16n8k16.row.col.f32.bf16.bf16.f32 "
        "{%0,%1,%2,%3}, {%4,%5,%6,%7}, {%8,%9}, {%0,%1,%2,%3};"
        : "+f"(c[0]), "+f"(c[1]), "+f"(c[2]), "+f"(c[3])
        : "r"(a[0]), "r"(a[1]), "r"(a[2]), "r"(a[3]), "r"(b0), "r"(b1));
}

__device__ __forceinline__ void split_bf16(float v, uint32_t& hbits, uint32_t& lbits) {
    __nv_bfloat16 h = __float2bfloat16(v);
    __nv_bfloat16 l = __float2bfloat16(v - __bfloat162float(h));
    hbits = (uint32_t)__bfloat16_as_ushort(h);
    lbits = (uint32_t)__bfloat16_as_ushort(l);
}

// ---------------------------------------------------------------------------
// Mask dtype detection (first 16MB scan = safe lower bound for all dtypes)
// ---------------------------------------------------------------------------
__global__ void reset_flags_kernel() { g_flags[0] = 0; g_flags[1] = 0; }

__global__ void detect_mask_kernel(const unsigned int* __restrict__ w, int nwords) {
    int notF = 0, notI = 0;
    int stride = gridDim.x * blockDim.x;
    for (int i = blockIdx.x * blockDim.x + threadIdx.x; i < nwords; i += stride) {
        unsigned int v = w[i];
        if (v != 0u && v != 0x3F800000u) notF = 1;
        if (v > 1u)                       notI = 1;
    }
    notF = __any_sync(0xFFFFFFFFu, notF);
    notI = __any_sync(0xFFFFFFFFu, notI);
    if ((threadIdx.x & 31) == 0) {
        if (notF) atomicOr(&g_flags[0], 1);
        if (notI) atomicOr(&g_flags[1], 1);
    }
}
__global__ void resolve_mode_kernel() {
    g_mode = (g_flags[0] == 0) ? 0 : ((g_flags[1] == 0) ? 1 : 2);
}

// ---------------------------------------------------------------------------
// Fold W_eff = W + delta*mask + 2*(B@A) → bf16 hi/lo
// ---------------------------------------------------------------------------
__global__ void fold_kernel(const float* __restrict__ W,
                            const float* __restrict__ lora_A,
                            const float* __restrict__ lora_B,
                            const float* __restrict__ delta,
                            const void*  __restrict__ maskp) {
    int o = blockIdx.x;
    __shared__ float br[16];
    if (threadIdx.x < 16) br[threadIdx.x] = lora_B[o * 16 + threadIdx.x] * kScaling;
    __syncthreads();

    const int mode = g_mode;
    const size_t rowoff = (size_t)o * DIN;

    for (int d = threadIdx.x * 4; d < DIN; d += blockDim.x * 4) {
        float4 w4 = *(const float4*)(W + rowoff + d);
        float4 dl = *(const float4*)(delta + rowoff + d);

        float m0, m1, m2, m3;
        if (mode == 0) {
            float4 mf = *(const float4*)((const float*)maskp + rowoff + d);
            m0 = mf.x; m1 = mf.y; m2 = mf.z; m3 = mf.w;
        } else if (mode == 1) {
            int4 mi = *(const int4*)((const int*)maskp + rowoff + d);
            m0 = mi.x ? 1.f : 0.f; m1 = mi.y ? 1.f : 0.f;
            m2 = mi.z ? 1.f : 0.f; m3 = mi.w ? 1.f : 0.f;
        } else {
            uchar4 mu = *(const uchar4*)((const unsigned char*)maskp + rowoff + d);
            m0 = mu.x ? 1.f : 0.f; m1 = mu.y ? 1.f : 0.f;
            m2 = mu.z ? 1.f : 0.f; m3 = mu.w ? 1.f : 0.f;
        }

        float l0 = 0.f, l1 = 0.f, l2 = 0.f, l3 = 0.f;
#pragma unroll
        for (int r = 0; r < 16; r++) {
            float4 a4 = *(const float4*)(lora_A + (size_t)r * DIN + d);
            float s = br[r];
            l0 = fmaf(s, a4.x, l0); l1 = fmaf(s, a4.y, l1);
            l2 = fmaf(s, a4.z, l2); l3 = fmaf(s, a4.w, l3);
        }

        float v0 = w4.x + dl.x * m0 + l0;
        float v1 = w4.y + dl.y * m1 + l1;
        float v2 = w4.z + dl.z * m2 + l2;
        float v3 = w4.w + dl.w * m3 + l3;

        uint32_t h0,h1,h2,h3,q0,q1,q2,q3;
        split_bf16(v0,h0,q0); split_bf16(v1,h1,q1);
        split_bf16(v2,h2,q2); split_bf16(v3,h3,q3);
        uint2 H = make_uint2(h0 | (h1<<16), h2 | (h3<<16));
        uint2 L = make_uint2(q0 | (q1<<16), q2 | (q3<<16));
        *(uint2*)((char*)g_Whi + (rowoff + d) * 2) = H;
        *(uint2*)((char*)g_Wlo + (rowoff + d) * 2) = L;
    }
}

// ---------------------------------------------------------------------------
// X → bf16 hi/lo split
// ---------------------------------------------------------------------------
__global__ void convert_x_kernel(const float* __restrict__ x) {
    size_t base = ((size_t)blockIdx.x * blockDim.x + threadIdx.x) * 4;
    float4 v = *(const float4*)(x + base);
    uint32_t h0,h1,h2,h3,q0,q1,q2,q3;
    split_bf16(v.x,h0,q0); split_bf16(v.y,h1,q1);
    split_bf16(v.z,h2,q2); split_bf16(v.w,h3,q3);
    uint2 H = make_uint2(h0 | (h1<<16), h2 | (h3<<16));
    uint2 L = make_uint2(q0 | (q1<<16), q2 | (q3<<16));
    *(uint2*)((char*)g_Xhi + base * 2) = H;
    *(uint2*)((char*)g_Xlo + base * 2) = L;
}

// ---------------------------------------------------------------------------
// HMMA bf16 GEMM: out[128x256 tile] = A'[128,12288]·B'[256,12288]^T + bias
// 8 warps (2m × 4n), warp tile 64x64, mma m16n8k16, 4-stage cp.async pipe.
// NOTE: swizzle applied to the FULL unswizzled byte offset per ldmatrix —
//       swz() does NOT commute with adding ks*32 (R4 bug).
// ---------------------------------------------------------------------------
__global__ __launch_bounds__(256, 1)
void gemm_kernel(const float* __restrict__ bias, float* __restrict__ out) {
    extern __shared__ __align__(1024) char smem[];
    const uint32_t sbase = smem_u32(smem);
    const int tid = threadIdx.x;
    const int lane = tid & 31;
    const int wid = tid >> 5;
    const int warpM = wid >> 2;           // 0..1
    const int warpN = wid & 3;            // 0..3
    const int bm = blockIdx.x * BM;       // m fastest → W stays L2-resident
    const int bn = blockIdx.y * BN;

    // ---- loader mapping: 12 x 16B per thread per chunk (A:4, B:8)
    int rowLA[4]; uint32_t dstLA[4]; int colLA[4];
#pragma unroll
    for (int i = 0; i < 4; i++) {
        int slot = tid + 256 * i;         // 0..1023
        rowLA[i] = slot >> 3;
        colLA[i] = (slot & 7) * 8;
        dstLA[i] = swz((uint32_t)(rowLA[i] * 128 + (slot & 7) * 16));
    }
    int rowLB[8]; uint32_t dstLB[8]; int colLB[8];
#pragma unroll
    for (int i = 0; i < 8; i++) {
        int slot = tid + 256 * i;         // 0..2047
        rowLB[i] = slot >> 3;             // 0..255
        colLB[i] = (slot & 7) * 8;
        dstLB[i] = swz((uint32_t)(rowLB[i] * 128 + (slot & 7) * 16));
    }

    // ---- ldmatrix per-lane UNswizzled byte offsets (row*128 + col part)
    const int arow  = (lane & 7) + ((lane >> 3) & 1) * 8;
    const int acol  = ((lane >> 4) & 1) * 16;           // byte
    const int brow  = (lane & 7) + ((lane >> 4) & 1) * 8;
    const int bcol  = ((lane >> 3) & 1) * 16;           // byte
    uint32_t baseA[4], baseB[4];
#pragma unroll
    for (int mt = 0; mt < 4; mt++)
        baseA[mt] = (uint32_t)((warpM * 64 + mt * 16 + arow) * 128 + acol);
#pragma unroll
    for (int p = 0; p < 4; p++)
        baseB[p] = (uint32_t)((warpN * 64 + p * 16 + brow) * 128 + bcol);

    float acc[4][8][4];
#pragma unroll
    for (int mt = 0; mt < 4; mt++)
#pragma unroll
        for (int nt = 0; nt < 8; nt++)
#pragma unroll
            for (int q = 0; q < 4; q++) acc[mt][nt][q] = 0.f;

    auto load_chunk = [&](int c, int stage) {
        const int seg = c >> 6;
        const int kk  = (c & 63) << 6;
        const __nv_bfloat16* As = (seg == 1) ? g_Xlo : g_Xhi;
        const __nv_bfloat16* Bs = (seg == 2) ? g_Wlo : g_Whi;
        const uint32_t aB = sbase + stage * STAGE_BYTES;
        const uint32_t bB = aB + A_BYTES;
#pragma unroll
        for (int i = 0; i < 4; i++)
            cp_async16(aB + dstLA[i], As + (size_t)(bm + rowLA[i]) * DIN + kk + colLA[i]);
#pragma unroll
        for (int i = 0; i < 8; i++)
            cp_async16(bB + dstLB[i], Bs + (size_t)(bn + rowLB[i]) * DIN + kk + colLB[i]);
    };

    // prologue: 3 chunks in flight
    load_chunk(0, 0); CP_COMMIT();
    load_chunk(1, 1); CP_COMMIT();
    load_chunk(2, 2); CP_COMMIT();

    for (int c = 0; c < NCHUNK; c++) {
        if (c + 2 < NCHUNK)      { CP_WAIT(2); }
        else if (c + 1 < NCHUNK) { CP_WAIT(1); }
        else                     { CP_WAIT(0); }
        __syncthreads();
        if (c + 3 < NCHUNK) { load_chunk(c + 3, (c + 3) & 3); CP_COMMIT(); }

        const uint32_t aB = sbase + (c & 3) * STAGE_BYTES;
        const uint32_t bB = aB + A_BYTES;
#pragma unroll
        for (int ks = 0; ks < 4; ks++) {
            uint32_t a[4][4];
#pragma unroll
            for (int mt = 0; mt < 4; mt++)
                ldsm_x4(a[mt], aB + swz(baseA[mt] + ks * 32));
            uint32_t b[4][4];
#pragma unroll
            for (int p = 0; p < 4; p++)
                ldsm_x4(b[p], bB + swz(baseB[p] + ks * 32));
#pragma unroll
            for (int mt = 0; mt < 4; mt++)
#pragma unroll
                for (int nt = 0; nt < 8; nt++) {
                    uint32_t b0 = b[nt >> 1][(nt & 1) * 2];
                    uint32_t b1 = b[nt >> 1][(nt & 1) * 2 + 1];
                    mma_bf16(acc[mt][nt], a[mt], b0, b1);
                }
        }
    }

    // ---- epilogue: add bias, float2 stores
    const int group = lane >> 2;
    const int tig   = lane & 3;
#pragma unroll
    for (int nt = 0; nt < 8; nt++) {
        const int col = bn + warpN * 64 + nt * 8 + tig * 2;
        const float2 bv = *(const float2*)(bias + col);
#pragma unroll
        for (int mt = 0; mt < 4; mt++) {
            const int row0 = bm + warpM * 64 + mt * 16 + group;
            float* p0 = out + (size_t)row0 * DOUT + col;
            float* p1 = out + (size_t)(row0 + 8) * DOUT + col;
            *(float2*)p0 = make_float2(acc[mt][nt][0] + bv.x, acc[mt][nt][1] + bv.y);
            *(float2*)p1 = make_float2(acc[mt][nt][2] + bv.x, acc[mt][nt][3] + bv.y);
        }
    }
}

// ---------------------------------------------------------------------------
// Launch
// ---------------------------------------------------------------------------
extern "C" void kernel_launch(void* const* d_in, const int* in_sizes, int n_in,
                              void* d_out, int out_size) {
    const float* x      = (const float*)d_in[0];
    const float* W      = (const float*)d_in[1];
    const float* b      = (const float*)d_in[2];
    const float* lora_A = (const float*)d_in[3];
    const float* lora_B = (const float*)d_in[4];
    const float* delta  = (const float*)d_in[5];
    const void*  mask   = d_in[6];

    static bool attr_done = false;
    if (!attr_done) {
        cudaFuncSetAttribute(gemm_kernel,
                             cudaFuncAttributeMaxDynamicSharedMemorySize, SMEM_TOTAL);
        attr_done = true;
    }

    reset_flags_kernel<<<1, 1>>>();
    detect_mask_kernel<<<256, 256>>>((const unsigned int*)mask, 4 * 1024 * 1024);
    resolve_mode_kernel<<<1, 1>>>();

    fold_kernel<<<DOUT, 256>>>(W, lora_A, lora_B, delta, mask);
    convert_x_kernel<<<(MTOT * DIN) / 4 / 256, 256>>>(x);

    dim3 grid(MTOT / BM, DOUT / BN);   // (64, 16), m fastest
    gemm_kernel<<<grid, 256, SMEM_TOTAL>>>(b, (float*)d_out);
}